// round 16
// baseline (speedup 1.0000x reference)
#include <cuda_runtime.h>
#include <cuda_bf16.h>
#include <math.h>
#include <stdint.h>

typedef unsigned short u16;

// Problem constants
constexpr int Bb = 4;
constexpr int T  = 2048;
constexpr int F  = 256;
constexpr int H  = 4;
constexpr int C  = 78;
constexpr int DK = 64;
constexpr int HALF = 38;
constexpr int WN = H * C;         // 312
constexpr int M  = Bb * T;        // 8192

constexpr float SCALE_Q = 0.18033688011112042f;  // 0.125 * log2(e)
constexpr float LOG2E   = 1.4426950408889634f;

// fp32 scratch
__device__ float g_vl[M * F];
__device__ float g_w [M * WN];
// bf16 tensors
__device__ u16 g_t1h[M * F];
__device__ u16 g_xlh[M * F], g_xll[M * F];
__device__ u16 g_xh [M * F], g_xl2[M * F];
__device__ u16 g_oh [M * F], g_ol [M * F];
__device__ u16 g_qh[M * F];
__device__ u16 g_kh[M * F];
__device__ u16 g_vh[M * F], g_vlo[M * F];

// ---------------- helpers ----------------
__device__ __forceinline__ uint32_t smem_u32(const void* p) {
    uint32_t a;
    asm("{ .reg .u64 t; cvta.to.shared.u64 t, %1; cvt.u32.u64 %0, t; }" : "=r"(a) : "l"(p));
    return a;
}
__device__ __forceinline__ void ldsm_x4(uint32_t* r, uint32_t a) {
    asm volatile("ldmatrix.sync.aligned.m8n8.x4.shared.b16 {%0,%1,%2,%3}, [%4];"
        : "=r"(r[0]), "=r"(r[1]), "=r"(r[2]), "=r"(r[3]) : "r"(a));
}
__device__ __forceinline__ void ldsm_x4t(uint32_t* r, uint32_t a) {
    asm volatile("ldmatrix.sync.aligned.m8n8.x4.trans.shared.b16 {%0,%1,%2,%3}, [%4];"
        : "=r"(r[0]), "=r"(r[1]), "=r"(r[2]), "=r"(r[3]) : "r"(a));
}
__device__ __forceinline__ void mma_bf(float* c, const uint32_t* a, const uint32_t* b) {
    asm volatile("mma.sync.aligned.m16n8k16.row.col.f32.bf16.bf16.f32 "
        "{%0,%1,%2,%3}, {%4,%5,%6,%7}, {%8,%9}, {%0,%1,%2,%3};"
        : "+f"(c[0]), "+f"(c[1]), "+f"(c[2]), "+f"(c[3])
        : "r"(a[0]), "r"(a[1]), "r"(a[2]), "r"(a[3]), "r"(b[0]), "r"(b[1]));
}
__device__ __forceinline__ uint32_t pack_bf16x2(float lo, float hi) {
    uint32_t r; asm("cvt.rn.bf16x2.f32 %0, %1, %2;" : "=r"(r) : "f"(hi), "f"(lo)); return r;
}
__device__ __forceinline__ float bf_lo_f(uint32_t p) { return __uint_as_float(p << 16); }
__device__ __forceinline__ float bf_hi_f(uint32_t p) { return __uint_as_float(p & 0xffff0000u); }
__device__ __forceinline__ void cp16(uint32_t smem_dst, const void* gptr) {
    asm volatile("cp.async.cg.shared.global [%0], [%1], 16;" :: "r"(smem_dst), "l"(gptr));
}
__device__ __forceinline__ void cp_commit() { asm volatile("cp.async.commit_group;" ::: "memory"); }
template <int N_> __device__ __forceinline__ void cp_wait() {
    asm volatile("cp.async.wait_group %0;" :: "n"(N_) : "memory");
}

// ---------------------------------------------------------------------------
// Pipelined GEMM mainloop (R12 config: 512 threads, 128x128 tile, warp 32x32).
// PASSES=1|3. AFMT: 0=f32 A (convert), 1=bf16-hi A, 2=bf16 pair A.
// ---------------------------------------------------------------------------
constexpr int GEMM_BUF  = 71680;
constexpr int GEMM_SMEM = 2 * GEMM_BUF;       // 143360

template <int PASSES, int AFMT>
__device__ __forceinline__ void gemm_main(
    const void* A0v, const void* A1v, const float* __restrict__ W,
    int N, int row0, int col0, char* smem, uint32_t sb, float c[2][4][4])
{
    constexpr uint32_t AH = 0, AL = 18432, BH = 36864, BL = 54272;
    constexpr int LDA = 72, LDB = 136;
    const float* Af  = (const float*)A0v;
    const u16* Ah16  = (const u16*)A0v;
    const u16* Al16  = (const u16*)A1v;
    const int tid  = threadIdx.x;
    const int wid  = tid >> 5;
    const int lane = tid & 31;
    const int warp_m = (wid & 3) * 32;
    const int warp_n = (wid >> 2) * 32;
    const int arow = lane & 15, acol8 = (lane >> 4) * 8;
    const int brow = lane & 15, bco = (lane & 16) >> 1;

    float4 aR[4], bR[4];
    uint4  aU[2], aU2[2];

    auto loadChunk = [&](int kc) {
        const int k0 = kc * 64;
        if (AFMT == 0) {
            #pragma unroll
            for (int p = 0; p < 4; p++) {
                int i = tid + p * 512;
                int r = i >> 4, c4 = (i & 15) * 4;
                aR[p] = *(const float4*)(Af + (size_t)(row0 + r) * 256 + k0 + c4);
            }
        } else {
            #pragma unroll
            for (int p = 0; p < 2; p++) {
                int i = tid + p * 512;
                int r = i >> 3, c8 = (i & 7) * 8;
                aU[p] = *(const uint4*)(Ah16 + (size_t)(row0 + r) * 256 + k0 + c8);
                if (AFMT == 2)
                    aU2[p] = *(const uint4*)(Al16 + (size_t)(row0 + r) * 256 + k0 + c8);
            }
        }
        #pragma unroll
        for (int p = 0; p < 4; p++) {
            int i = tid + p * 512;
            int r = i >> 5, c4 = (i & 31) * 4;
            int n0c = col0 + c4;
            bR[p] = (n0c < N) ? *(const float4*)(W + (size_t)(k0 + r) * N + n0c)
                              : make_float4(0.f, 0.f, 0.f, 0.f);
        }
    };
    auto storeChunk = [&](uint32_t base) {
        if (AFMT == 0) {
            #pragma unroll
            for (int p = 0; p < 4; p++) {
                int i = tid + p * 512;
                int r = i >> 4, c4 = (i & 15) * 4;
                float4 a = aR[p];
                uint32_t h01 = pack_bf16x2(a.x, a.y), h23 = pack_bf16x2(a.z, a.w);
                uint32_t off = (uint32_t)(r * LDA + c4) * 2;
                *(uint2*)(smem + base + AH + off) = make_uint2(h01, h23);
                if (PASSES == 3) {
                    uint32_t l01 = pack_bf16x2(a.x - bf_lo_f(h01), a.y - bf_hi_f(h01));
                    uint32_t l23 = pack_bf16x2(a.z - bf_lo_f(h23), a.w - bf_hi_f(h23));
                    *(uint2*)(smem + base + AL + off) = make_uint2(l01, l23);
                }
            }
        } else {
            #pragma unroll
            for (int p = 0; p < 2; p++) {
                int i = tid + p * 512;
                int r = i >> 3, c8 = (i & 7) * 8;
                uint32_t off = (uint32_t)(r * LDA + c8) * 2;
                *(uint4*)(smem + base + AH + off) = aU[p];
                if (AFMT == 2)
                    *(uint4*)(smem + base + AL + off) = aU2[p];
            }
        }
        #pragma unroll
        for (int p = 0; p < 4; p++) {
            int i = tid + p * 512;
            int r = i >> 5, c4 = (i & 31) * 4;
            float4 w = bR[p];
            uint32_t h01 = pack_bf16x2(w.x, w.y), h23 = pack_bf16x2(w.z, w.w);
            uint32_t off = (uint32_t)(r * LDB + c4) * 2;
            *(uint2*)(smem + base + BH + off) = make_uint2(h01, h23);
            if (PASSES == 3) {
                uint32_t l01 = pack_bf16x2(w.x - bf_lo_f(h01), w.y - bf_hi_f(h01));
                uint32_t l23 = pack_bf16x2(w.z - bf_lo_f(h23), w.w - bf_hi_f(h23));
                *(uint2*)(smem + base + BL + off) = make_uint2(l01, l23);
            }
        }
    };

    loadChunk(0);
    storeChunk(0);
    __syncthreads();

    for (int kc = 0; kc < 4; kc++) {
        const uint32_t cur = (kc & 1) ? GEMM_BUF : 0;
        if (kc < 3) loadChunk(kc + 1);

        #pragma unroll
        for (int ks = 0; ks < 4; ks++) {
            uint32_t ah[2][4], al[2][4];
            #pragma unroll
            for (int i = 0; i < 2; i++) {
                uint32_t ao = cur + AH + (uint32_t)((warp_m + 16 * i + arow) * LDA + ks * 16 + acol8) * 2;
                ldsm_x4(ah[i], sb + ao);
                if (PASSES == 3) ldsm_x4(al[i], sb + ao + (AL - AH));
            }
            uint32_t bh[2][4], bl[2][4];
            #pragma unroll
            for (int jp = 0; jp < 2; jp++) {
                uint32_t bo = cur + BH + (uint32_t)((ks * 16 + brow) * LDB + warp_n + 16 * jp + bco) * 2;
                ldsm_x4t(bh[jp], sb + bo);
                if (PASSES == 3) ldsm_x4t(bl[jp], sb + bo + (BL - BH));
            }
            #pragma unroll
            for (int pass = 0; pass < PASSES; pass++) {
                #pragma unroll
                for (int i = 0; i < 2; i++) {
                    const uint32_t* aa = (pass == 2) ? al[i] : ah[i];
                    #pragma unroll
                    for (int jp = 0; jp < 2; jp++) {
                        const uint32_t* bb = (pass == 1) ? bl[jp] : bh[jp];
                        mma_bf(c[i][2*jp],   aa, bb);
                        mma_bf(c[i][2*jp+1], aa, bb + 2);
                    }
                }
            }
        }

        if (kc < 3) {
            storeChunk((kc & 1) ? 0 : GEMM_BUF);
            __syncthreads();
        }
    }
}

// ---------------- epilogues ----------------
__device__ __forceinline__ void epi_f32(
    float c[2][4][4], float* __restrict__ Cout, const float* __restrict__ bias,
    int N, int row0, int col0, bool relu, float sc)
{
    const int wid  = threadIdx.x >> 5;
    const int lane = threadIdx.x & 31;
    const int warp_m = (wid & 3) * 32;
    const int warp_n = (wid >> 2) * 32;
    const int g = lane >> 2, t2 = (lane & 3) * 2;
    #pragma unroll
    for (int j = 0; j < 4; j++) {
        int col = col0 + warp_n + 8 * j + t2;
        if (col >= N) continue;
        float2 b2 = make_float2(0.f, 0.f);
        if (bias) b2 = *(const float2*)(bias + col);
        #pragma unroll
        for (int i = 0; i < 2; i++) {
            int rl = row0 + warp_m + 16 * i + g;
            float2 v0 = make_float2(c[i][j][0] * sc + b2.x, c[i][j][1] * sc + b2.y);
            float2 v1 = make_float2(c[i][j][2] * sc + b2.x, c[i][j][3] * sc + b2.y);
            if (relu) {
                v0.x = fmaxf(v0.x, 0.f); v0.y = fmaxf(v0.y, 0.f);
                v1.x = fmaxf(v1.x, 0.f); v1.y = fmaxf(v1.y, 0.f);
            }
            *(float2*)(Cout + (size_t)rl * N + col)       = v0;
            *(float2*)(Cout + (size_t)(rl + 8) * N + col) = v1;
        }
    }
}

__device__ __forceinline__ void epi_hi(
    float c[2][4][4], u16* __restrict__ Ho, const float* __restrict__ bias,
    float sc, bool relu, int row0, int col0)
{
    const int wid  = threadIdx.x >> 5;
    const int lane = threadIdx.x & 31;
    const int warp_m = (wid & 3) * 32;
    const int warp_n = (wid >> 2) * 32;
    const int g = lane >> 2, t2 = (lane & 3) * 2;
    #pragma unroll
    for (int j = 0; j < 4; j++) {
        int col = col0 + warp_n + 8 * j + t2;
        float2 b2 = make_float2(0.f, 0.f);
        if (bias) b2 = *(const float2*)(bias + col);
        #pragma unroll
        for (int i = 0; i < 2; i++) {
            int rl = row0 + warp_m + 16 * i + g;
            float v0 = (c[i][j][0] + b2.x) * sc, v1 = (c[i][j][1] + b2.y) * sc;
            float v2 = (c[i][j][2] + b2.x) * sc, v3 = (c[i][j][3] + b2.y) * sc;
            if (relu) {
                v0 = fmaxf(v0, 0.f); v1 = fmaxf(v1, 0.f);
                v2 = fmaxf(v2, 0.f); v3 = fmaxf(v3, 0.f);
            }
            *(uint32_t*)(Ho + (size_t)rl * 256 + col)       = pack_bf16x2(v0, v1);
            *(uint32_t*)(Ho + (size_t)(rl + 8) * 256 + col) = pack_bf16x2(v2, v3);
        }
    }
}

__device__ __forceinline__ void epi_pair(
    float c[2][4][4], u16* __restrict__ Ho, u16* __restrict__ Lo,
    const float* __restrict__ bias, int row0, int col0)
{
    const int wid  = threadIdx.x >> 5;
    const int lane = threadIdx.x & 31;
    const int warp_m = (wid & 3) * 32;
    const int warp_n = (wid >> 2) * 32;
    const int g = lane >> 2, t2 = (lane & 3) * 2;
    #pragma unroll
    for (int j = 0; j < 4; j++) {
        int col = col0 + warp_n + 8 * j + t2;
        float2 b2 = make_float2(0.f, 0.f);
        if (bias) b2 = *(const float2*)(bias + col);
        #pragma unroll
        for (int i = 0; i < 2; i++) {
            int rl = row0 + warp_m + 16 * i + g;
            float v0 = c[i][j][0] + b2.x, v1 = c[i][j][1] + b2.y;
            float v2 = c[i][j][2] + b2.x, v3 = c[i][j][3] + b2.y;
            uint32_t h0 = pack_bf16x2(v0, v1);
            uint32_t l0 = pack_bf16x2(v0 - bf_lo_f(h0), v1 - bf_hi_f(h0));
            uint32_t h1 = pack_bf16x2(v2, v3);
            uint32_t l1 = pack_bf16x2(v2 - bf_lo_f(h1), v3 - bf_hi_f(h1));
            *(uint32_t*)(Ho + (size_t)rl * 256 + col)       = h0;
            *(uint32_t*)(Lo + (size_t)rl * 256 + col)       = l0;
            *(uint32_t*)(Ho + (size_t)(rl + 8) * 256 + col) = h1;
            *(uint32_t*)(Lo + (size_t)(rl + 8) * 256 + col) = l1;
        }
    }
}

// ---------------- GEMM kernels (R12 config) ----------------
__global__ __launch_bounds__(512, 1) void gemm13bf(
    const float* __restrict__ query, const float* __restrict__ w1,
    const float* __restrict__ value, const float* __restrict__ w3)
{
    extern __shared__ char smem[];
    const int sel  = blockIdx.x >> 1;
    const int col0 = (blockIdx.x & 1) * 128;
    const int row0 = blockIdx.y * 128;
    if (sel == 0) {
        float c[2][4][4] = {};
        gemm_main<1, 0>(query, nullptr, w1, 256, row0, col0, smem, smem_u32(smem), c);
        epi_hi(c, g_t1h, nullptr, 1.f, true, row0, col0);
    } else {
        float c[2][4][4] = {};
        gemm_main<3, 0>(value, nullptr, w3, 256, row0, col0, smem, smem_u32(smem), c);
        epi_f32(c, g_vl, nullptr, 256, row0, col0, false, 1.f);
    }
}

__global__ __launch_bounds__(512, 1) void gemm_w2k(const float* __restrict__ w2)
{
    extern __shared__ char smem[];
    const int col0 = blockIdx.x * 104;
    const int row0 = blockIdx.y * 128;
    float c[2][4][4] = {};
    gemm_main<1, 1>(g_t1h, nullptr, w2, WN, row0, col0, smem, smem_u32(smem), c);
    epi_f32(c, g_w, nullptr, WN, row0, col0, false, LOG2E);
}

__global__ __launch_bounds__(512, 1) void gemm_wlk(const float* __restrict__ wl)
{
    extern __shared__ char smem[];
    const int col0 = blockIdx.x * 128;
    const int row0 = blockIdx.y * 128;
    float c[2][4][4] = {};
    gemm_main<3, 2>(g_xlh, g_xll, wl, 256, row0, col0, smem, smem_u32(smem), c);
    epi_pair(c, g_xh, g_xl2, nullptr, row0, col0);
}

__global__ __launch_bounds__(512, 1) void qkv_bf(
    const float* __restrict__ wq, const float* __restrict__ bq,
    const float* __restrict__ wk, const float* __restrict__ bk,
    const float* __restrict__ wv, const float* __restrict__ bv)
{
    extern __shared__ char smem[];
    const int wsel = blockIdx.x >> 1;
    const int col0 = (blockIdx.x & 1) * 128;
    const int row0 = blockIdx.y * 128;
    if (wsel == 0) {
        float c[2][4][4] = {};
        gemm_main<1, 1>(g_xh, nullptr, wq, 256, row0, col0, smem, smem_u32(smem), c);
        epi_hi(c, g_qh, bq, SCALE_Q, false, row0, col0);
    } else if (wsel == 1) {
        float c[2][4][4] = {};
        gemm_main<1, 1>(g_xh, nullptr, wk, 256, row0, col0, smem, smem_u32(smem), c);
        epi_hi(c, g_kh, bk, 1.f, false, row0, col0);
    } else {
        float c[2][4][4] = {};
        gemm_main<3, 2>(g_xh, g_xl2, wv, 256, row0, col0, smem, smem_u32(smem), c);
        epi_pair(c, g_vh, g_vlo, bv, row0, col0);
    }
}

__global__ __launch_bounds__(512, 1) void gemm_wok(
    const float* __restrict__ wo, const float* __restrict__ bo, float* __restrict__ out)
{
    extern __shared__ char smem[];
    const int col0 = blockIdx.x * 128;
    const int row0 = blockIdx.y * 128;
    float c[2][4][4] = {};
    gemm_main<3, 2>(g_oh, g_ol, wo, 256, row0, col0, smem, smem_u32(smem), c);
    epi_f32(c, out, bo, 256, row0, col0, false, 1.f);
}

// ---------------------------------------------------------------------------
// LDSA local-window attention — 32-row tiles, no-max exp2 softmax (R12).
// ---------------------------------------------------------------------------
__global__ __launch_bounds__(256) void ldsa_kernel()
{
    __shared__ float vsm[109][64];
    __shared__ float psm[8][80];

    const int bh = blockIdx.y;
    const int b = bh >> 2;
    const int h = bh & 3;
    const int t0 = blockIdx.x * 32;
    const int tid = threadIdx.x;

    for (int idx = tid; idx < 109 * 16; idx += 256) {
        int r  = idx >> 4;
        int dg = (idx & 15) * 4;
        int j  = t0 - HALF + r;
        float4 v = make_float4(0.f, 0.f, 0.f, 0.f);
        if (j >= 0 && j < T)
            v = *(const float4*)(g_vl + (size_t)(b * T + j) * F + h * DK + dg);
        *(float4*)&vsm[r][dg] = v;
    }
    __syncthreads();

    const int warp = tid >> 5;
    const int lane = tid & 31;

    for (int it = 0; it < 4; it++) {
        const int tl = it * 8 + warp;
        const int t  = t0 + tl;

        float e[3];
        float s = 0.f;
        #pragma unroll
        for (int u = 0; u < 3; u++) {
            int c = lane + u * 32;
            float val = -3.0e38f;
            if (c < C) {
                int j = t - HALF + c;
                if (j >= 0 && j < T)
                    val = g_w[(size_t)(b * T + t) * WN + h * C + c];
            }
            e[u] = exp2f(val);
            s += e[u];
        }
        #pragma unroll
        for (int off = 16; off > 0; off >>= 1)
            s += __shfl_xor_sync(0xffffffffu, s, off);
        float inv = 1.f / s;

        #pragma unroll
        for (int u = 0; u < 3; u++) {
            int c = lane + u * 32;
            if (c < C) psm[warp][c] = e[u] * inv;
        }
        __syncwarp();

        const int d0 = lane * 2;
        float a0 = 0.f, a1 = 0.f;
        #pragma unroll 2
        for (int c = 0; c < C; c++) {
            float p = psm[warp][c];
            float2 v = *(const float2*)&vsm[tl + c][d0];
            a0 += p * v.x;
            a1 += p * v.y;
        }
        size_t idx = (size_t)(b * T + t) * F + h * DK + d0;
        uint32_t hh = pack_bf16x2(a0, a1);
        uint32_t ll = pack_bf16x2(a0 - bf_lo_f(hh), a1 - bf_hi_f(hh));
        *(uint32_t*)(g_xlh + idx) = hh;
        *(uint32_t*)(g_xll + idx) = ll;
        __syncwarp();
    }
}

// ---------------------------------------------------------------------------
// Flash-attention MHA, SMALL-CTA version for multi-CTA/SM overlap:
// 128 threads (4 warps x 16 q-rows = 64 rows/CTA), 64-col s-tiles (32 iters),
// double-buffered K/V, no-max softmax, Q fragments hoisted.
// smem 64512 -> 3 CTAs/SM co-resident.
// ---------------------------------------------------------------------------
constexpr int KV_BUF     = 27648;                 // KH | VH | VL, 9216 each
constexpr int FLASH_SMEM = 9216 + 2 * KV_BUF;     // 64512

__global__ __launch_bounds__(128, 3) void flash_mma()
{
    extern __shared__ char smem[];
    const uint32_t sb = smem_u32(smem);
    constexpr uint32_t QH = 0, KV0 = 9216;
    constexpr int LDS = 72;

    const int bh = blockIdx.y;
    const int b = bh >> 2;
    const int h = bh & 3;
    const int t0 = blockIdx.x * 64;
    const int tid  = threadIdx.x;
    const int wid  = tid >> 5;
    const int lane = tid & 31;
    const int g  = lane >> 2;
    const int t2 = (lane & 3) * 2;

    // stage Q hi (64 rows)
    for (int i = tid; i < 512; i += 128) {
        int r = i >> 3, d8 = (i & 7) * 8;
        size_t go = (size_t)(b * T + t0 + r) * 256 + h * 64 + d8;
        *(uint4*)(smem + QH + (uint32_t)(r * LDS + d8) * 2) = *(const uint4*)(g_qh + go);
    }

    auto prefetchKV = [&](int st) {
        const uint32_t base = KV0 + (uint32_t)(st & 1) * KV_BUF;
        const int s0 = st * 64;
        #pragma unroll
        for (int p = 0; p < 4; p++) {
            int i = tid + p * 128;
            int r = i >> 3, d8 = (i & 7) * 8;
            size_t go = (size_t)(b * T + s0 + r) * 256 + h * 64 + d8;
            uint32_t so = base + (uint32_t)(r * LDS + d8) * 2;
            cp16(sb + so,        g_kh  + go);
            cp16(sb + so + 9216, g_vh  + go);
            cp16(sb + so + 18432, g_vlo + go);
        }
        cp_commit();
    };

    prefetchKV(0);
    __syncthreads();   // Q staged before fragment hoist

    const int arow = lane & 15, acol8 = (lane >> 4) * 8;
    const int brow2 = (lane & 7) | ((lane & 16) >> 1);
    const int bco = lane & 8;
    const int vco = (lane & 16) >> 1;

    // hoist Q fragments (rows 16*wid, tile-invariant)
    uint32_t qf[4][4];
    #pragma unroll
    for (int ks = 0; ks < 4; ks++)
        ldsm_x4(qf[ks], sb + QH + (uint32_t)((16 * wid + arow) * LDS + ks * 16 + acol8) * 2);

    float o[8][4] = {};
    float l0 = 0.f, l1 = 0.f;

    for (int st = 0; st < 32; st++) {
        cp_wait<0>();
        __syncthreads();           // buffer st%2 full; all warps done with st-1
        if (st + 1 < 32) prefetchKV(st + 1);   // writes buffer (st+1)%2

        const uint32_t KHb = sb + KV0 + (uint32_t)(st & 1) * KV_BUF;
        const uint32_t VHb = KHb + 9216, VLb = KHb + 18432;

        // ---- S = Q @ K^T over 64 s-cols, single bf16 pass ----
        float s[8][4] = {};
        #pragma unroll
        for (int ks = 0; ks < 4; ks++) {
            #pragma unroll
            for (int jp = 0; jp < 4; jp++) {
                uint32_t kh[4];
                ldsm_x4(kh, KHb + (uint32_t)((16 * jp + brow2) * LDS + ks * 16 + bco) * 2);
                mma_bf(s[2*jp],   qf[ks], kh);
                mma_bf(s[2*jp+1], qf[ks], kh + 2);
            }
        }

        // ---- softmax numerator, no max shift ----
        float rs0 = 0.f, rs1 = 0.f;
        uint32_t ph[4][4], pl[4][4];
        #pragma unroll
        for (int kb = 0; kb < 4; kb++) {
            float e00 = exp2f(s[2*kb][0]),   e01 = exp2f(s[2*kb][1]);
            float e02 = exp2f(s[2*kb][2]),   e03 = exp2f(s[2*kb][3]);
            float e10 = exp2f(s[2*kb+1][0]), e11 = exp2f(s[2*kb+1][1]);
            float e12 = exp2f(s[2*kb+1][2]), e13 = exp2f(s[2*kb+1][3]);
            rs0 += e00 + e01 + e10 + e11;
            rs1 += e02 + e03 + e12 + e13;
            ph[kb][0] = pack_bf16x2(e00, e01);
            ph[kb][1] = pack_bf16x2(e02, e03);
            ph[kb][2] = pack_bf16x2(e10, e11);
            ph[kb][3] = pack_bf16x2(e12, e13);
            pl[kb][0] = pack_bf16x2(e00 - bf_lo_f(ph[kb][0]), e01 - bf_hi_f(ph[kb][0]));
            pl[kb][1] = pack_bf16x2(e02 - bf_lo_f(ph[kb][1]), e03 - bf_hi_f(ph[kb][1]));
            pl[kb][2] = pack_bf16x2(e10 - bf_lo_f(ph[kb][2]), e11 - bf_hi_f(ph[kb][2]));
            pl[kb][3] = pack_bf16x2(e12 - bf_lo_f(ph[kb][3]), e13 - bf_hi_f(ph[kb][3]));
        }
        rs0 += __shfl_xor_sync(0xffffffffu, rs0, 1);
        rs0 += __shfl_xor_sync(0xffffffffu, rs0, 2);
        rs1 += __shfl_xor_sync(0xffffffffu, rs1, 1);
        rs1 += __shfl_xor_sync(0xffffffffu, rs1, 2);
        l0 += rs0;
        l1 += rs1;

        // ---- O += P @ V (3-pass, pass-outer, V fragments preloaded) ----
        #pragma unroll
        for (int kb = 0; kb < 4; kb++) {
            uint32_t vh[4][4], vl[4][4];
            #pragma unroll
            for (int jp = 0; jp < 4; jp++) {
                uint32_t vo = (uint32_t)((kb * 16 + (lane & 15)) * LDS + 16 * jp + vco) * 2;
                ldsm_x4t(vh[jp], VHb + vo);
                ldsm_x4t(vl[jp], VLb + vo);
            }
            #pragma unroll
            for (int pass = 0; pass < 3; pass++) {
                const uint32_t* pa = (pass == 2) ? pl[kb] : ph[kb];
                #pragma unroll
                for (int jp = 0; jp < 4; jp++) {
                    const uint32_t* vb = (pass == 1) ? vl[jp] : vh[jp];
                    mma_bf(o[2*jp],   pa, vb);
                    mma_bf(o[2*jp+1], pa, vb + 2);
                }
            }
        }
    }

    const float inv0 = 1.f / l0, inv1 = 1.f / l1;
    const int r0 = t0 + 16 * wid + g;
    #pragma unroll
    for (int j = 0; j < 8; j++) {
        int col = h * DK + 8 * j + t2;
        float v0 = o[j][0] * inv0, v1 = o[j][1] * inv0;
        float v2 = o[j][2] * inv1, v3 = o[j][3] * inv1;
        uint32_t h0  = pack_bf16x2(v0, v1);
        uint32_t l0p = pack_bf16x2(v0 - bf_lo_f(h0), v1 - bf_hi_f(h0));
        uint32_t h1  = pack_bf16x2(v2, v3);
        uint32_t l1p = pack_bf16x2(v2 - bf_lo_f(h1), v3 - bf_hi_f(h1));
        size_t i0 = (size_t)(b * T + r0) * F + col;
        size_t i1 = (size_t)(b * T + r0 + 8) * F + col;
        *(uint32_t*)(g_oh + i0) = h0;
        *(uint32_t*)(g_ol + i0) = l0p;
        *(uint32_t*)(g_oh + i1) = h1;
        *(uint32_t*)(g_ol + i1) = l1p;
    }
}

// ---------------------------------------------------------------------------
extern "C" void kernel_launch(void* const* d_in, const int* in_sizes, int n_in,
                              void* d_out, int out_size)
{
    const float* query  = (const float*)d_in[0];
    const float* value  = (const float*)d_in[2];
    const float* w1     = (const float*)d_in[4];
    const float* w2     = (const float*)d_in[5];
    const float* w3     = (const float*)d_in[6];
    const float* w_ldsa = (const float*)d_in[7];
    const float* wq     = (const float*)d_in[8];
    const float* bq     = (const float*)d_in[9];
    const float* wk     = (const float*)d_in[10];
    const float* bk     = (const float*)d_in[11];
    const float* wv     = (const float*)d_in[12];
    const float* bv     = (const float*)d_in[13];
    const float* wo     = (const float*)d_in[14];
    const float* bo     = (const float*)d_in[15];
    float* out = (float*)d_out;

    cudaFuncSetAttribute(gemm13bf,  cudaFuncAttributeMaxDynamicSharedMemorySize, GEMM_SMEM);
    cudaFuncSetAttribute(gemm_w2k,  cudaFuncAttributeMaxDynamicSharedMemorySize, GEMM_SMEM);
    cudaFuncSetAttribute(gemm_wlk,  cudaFuncAttributeMaxDynamicSharedMemorySize, GEMM_SMEM);
    cudaFuncSetAttribute(qkv_bf,    cudaFuncAttributeMaxDynamicSharedMemorySize, GEMM_SMEM);
    cudaFuncSetAttribute(gemm_wok,  cudaFuncAttributeMaxDynamicSharedMemorySize, GEMM_SMEM);
    cudaFuncSetAttribute(flash_mma, cudaFuncAttributeMaxDynamicSharedMemorySize, FLASH_SMEM);

    // LDSA stage
    gemm13bf<<<dim3(4, M / 128), 512, GEMM_SMEM>>>(query, w1, value, w3);
    gemm_w2k<<<dim3(3, M / 128), 512, GEMM_SMEM>>>(w2);
    ldsa_kernel<<<dim3(T / 32, Bb * H), 256>>>();
    gemm_wlk<<<dim3(2, M / 128), 512, GEMM_SMEM>>>(w_ldsa);

    // MHA stage
    qkv_bf<<<dim3(6, M / 128), 512, GEMM_SMEM>>>(wq, bq, wk, bk, wv, bv);
    flash_mma<<<dim3(T / 64, Bb * H), 128, FLASH_SMEM>>>();
    gemm_wok<<<dim3(2, M / 128), 512, GEMM_SMEM>>>(wo, bo, out);
}

// round 17
// speedup vs baseline: 1.0616x; 1.0616x over previous
#include <cuda_runtime.h>
#include <cuda_bf16.h>
#include <math.h>
#include <stdint.h>

typedef unsigned short u16;

// Problem constants
constexpr int Bb = 4;
constexpr int T  = 2048;
constexpr int F  = 256;
constexpr int H  = 4;
constexpr int C  = 78;
constexpr int DK = 64;
constexpr int HALF = 38;
constexpr int WN = H * C;         // 312
constexpr int M  = Bb * T;        // 8192

constexpr float SCALE_Q = 0.18033688011112042f;  // 0.125 * log2(e)
constexpr float LOG2E   = 1.4426950408889634f;

// scratch
__device__ float g_w [M * WN];                  // ldsa scores (pre-scaled by log2e)
__device__ u16 g_vwh[M * F], g_vwl[M * F];      // value @ w3 pair (ldsa V)
__device__ u16 g_t1h[M * F];
__device__ u16 g_xlh[M * F], g_xll[M * F];
__device__ u16 g_xh [M * F], g_xl2[M * F];
__device__ u16 g_oh [M * F], g_ol [M * F];
__device__ u16 g_qh[M * F];
__device__ u16 g_kh[M * F];
__device__ u16 g_vh[M * F], g_vlo[M * F];

// ---------------- helpers ----------------
__device__ __forceinline__ uint32_t smem_u32(const void* p) {
    uint32_t a;
    asm("{ .reg .u64 t; cvta.to.shared.u64 t, %1; cvt.u32.u64 %0, t; }" : "=r"(a) : "l"(p));
    return a;
}
__device__ __forceinline__ void ldsm_x4(uint32_t* r, uint32_t a) {
    asm volatile("ldmatrix.sync.aligned.m8n8.x4.shared.b16 {%0,%1,%2,%3}, [%4];"
        : "=r"(r[0]), "=r"(r[1]), "=r"(r[2]), "=r"(r[3]) : "r"(a));
}
__device__ __forceinline__ void ldsm_x4t(uint32_t* r, uint32_t a) {
    asm volatile("ldmatrix.sync.aligned.m8n8.x4.trans.shared.b16 {%0,%1,%2,%3}, [%4];"
        : "=r"(r[0]), "=r"(r[1]), "=r"(r[2]), "=r"(r[3]) : "r"(a));
}
__device__ __forceinline__ void mma_bf(float* c, const uint32_t* a, const uint32_t* b) {
    asm volatile("mma.sync.aligned.m16n8k16.row.col.f32.bf16.bf16.f32 "
        "{%0,%1,%2,%3}, {%4,%5,%6,%7}, {%8,%9}, {%0,%1,%2,%3};"
        : "+f"(c[0]), "+f"(c[1]), "+f"(c[2]), "+f"(c[3])
        : "r"(a[0]), "r"(a[1]), "r"(a[2]), "r"(a[3]), "r"(b[0]), "r"(b[1]));
}
__device__ __forceinline__ uint32_t pack_bf16x2(float lo, float hi) {
    uint32_t r; asm("cvt.rn.bf16x2.f32 %0, %1, %2;" : "=r"(r) : "f"(hi), "f"(lo)); return r;
}
__device__ __forceinline__ float bf_lo_f(uint32_t p) { return __uint_as_float(p << 16); }
__device__ __forceinline__ float bf_hi_f(uint32_t p) { return __uint_as_float(p & 0xffff0000u); }
__device__ __forceinline__ void cp16(uint32_t smem_dst, const void* gptr) {
    asm volatile("cp.async.cg.shared.global [%0], [%1], 16;" :: "r"(smem_dst), "l"(gptr));
}
__device__ __forceinline__ void cp_commit() { asm volatile("cp.async.commit_group;" ::: "memory"); }
template <int N_> __device__ __forceinline__ void cp_wait() {
    asm volatile("cp.async.wait_group %0;" :: "n"(N_) : "memory");
}

// ---------------------------------------------------------------------------
// Pipelined GEMM mainloop (R12 config: 512 threads, 128x128 tile, warp 32x32).
// PASSES=1|3. AFMT: 0=f32 A (convert), 1=bf16-hi A, 2=bf16 pair A.
// ---------------------------------------------------------------------------
constexpr int GEMM_BUF  = 71680;
constexpr int GEMM_SMEM = 2 * GEMM_BUF;       // 143360

template <int PASSES, int AFMT>
__device__ __forceinline__ void gemm_main(
    const void* A0v, const void* A1v, const float* __restrict__ W,
    int N, int row0, int col0, char* smem, uint32_t sb, float c[2][4][4])
{
    constexpr uint32_t AH = 0, AL = 18432, BH = 36864, BL = 54272;
    constexpr int LDA = 72, LDB = 136;
    const float* Af  = (const float*)A0v;
    const u16* Ah16  = (const u16*)A0v;
    const u16* Al16  = (const u16*)A1v;
    const int tid  = threadIdx.x;
    const int wid  = tid >> 5;
    const int lane = tid & 31;
    const int warp_m = (wid & 3) * 32;
    const int warp_n = (wid >> 2) * 32;
    const int arow = lane & 15, acol8 = (lane >> 4) * 8;
    const int brow = lane & 15, bco = (lane & 16) >> 1;

    float4 aR[4], bR[4];
    uint4  aU[2], aU2[2];

    auto loadChunk = [&](int kc) {
        const int k0 = kc * 64;
        if (AFMT == 0) {
            #pragma unroll
            for (int p = 0; p < 4; p++) {
                int i = tid + p * 512;
                int r = i >> 4, c4 = (i & 15) * 4;
                aR[p] = *(const float4*)(Af + (size_t)(row0 + r) * 256 + k0 + c4);
            }
        } else {
            #pragma unroll
            for (int p = 0; p < 2; p++) {
                int i = tid + p * 512;
                int r = i >> 3, c8 = (i & 7) * 8;
                aU[p] = *(const uint4*)(Ah16 + (size_t)(row0 + r) * 256 + k0 + c8);
                if (AFMT == 2)
                    aU2[p] = *(const uint4*)(Al16 + (size_t)(row0 + r) * 256 + k0 + c8);
            }
        }
        #pragma unroll
        for (int p = 0; p < 4; p++) {
            int i = tid + p * 512;
            int r = i >> 5, c4 = (i & 31) * 4;
            int n0c = col0 + c4;
            bR[p] = (n0c < N) ? *(const float4*)(W + (size_t)(k0 + r) * N + n0c)
                              : make_float4(0.f, 0.f, 0.f, 0.f);
        }
    };
    auto storeChunk = [&](uint32_t base) {
        if (AFMT == 0) {
            #pragma unroll
            for (int p = 0; p < 4; p++) {
                int i = tid + p * 512;
                int r = i >> 4, c4 = (i & 15) * 4;
                float4 a = aR[p];
                uint32_t h01 = pack_bf16x2(a.x, a.y), h23 = pack_bf16x2(a.z, a.w);
                uint32_t off = (uint32_t)(r * LDA + c4) * 2;
                *(uint2*)(smem + base + AH + off) = make_uint2(h01, h23);
                if (PASSES == 3) {
                    uint32_t l01 = pack_bf16x2(a.x - bf_lo_f(h01), a.y - bf_hi_f(h01));
                    uint32_t l23 = pack_bf16x2(a.z - bf_lo_f(h23), a.w - bf_hi_f(h23));
                    *(uint2*)(smem + base + AL + off) = make_uint2(l01, l23);
                }
            }
        } else {
            #pragma unroll
            for (int p = 0; p < 2; p++) {
                int i = tid + p * 512;
                int r = i >> 3, c8 = (i & 7) * 8;
                uint32_t off = (uint32_t)(r * LDA + c8) * 2;
                *(uint4*)(smem + base + AH + off) = aU[p];
                if (AFMT == 2)
                    *(uint4*)(smem + base + AL + off) = aU2[p];
            }
        }
        #pragma unroll
        for (int p = 0; p < 4; p++) {
            int i = tid + p * 512;
            int r = i >> 5, c4 = (i & 31) * 4;
            float4 w = bR[p];
            uint32_t h01 = pack_bf16x2(w.x, w.y), h23 = pack_bf16x2(w.z, w.w);
            uint32_t off = (uint32_t)(r * LDB + c4) * 2;
            *(uint2*)(smem + base + BH + off) = make_uint2(h01, h23);
            if (PASSES == 3) {
                uint32_t l01 = pack_bf16x2(w.x - bf_lo_f(h01), w.y - bf_hi_f(h01));
                uint32_t l23 = pack_bf16x2(w.z - bf_lo_f(h23), w.w - bf_hi_f(h23));
                *(uint2*)(smem + base + BL + off) = make_uint2(l01, l23);
            }
        }
    };

    loadChunk(0);
    storeChunk(0);
    __syncthreads();

    for (int kc = 0; kc < 4; kc++) {
        const uint32_t cur = (kc & 1) ? GEMM_BUF : 0;
        if (kc < 3) loadChunk(kc + 1);

        #pragma unroll
        for (int ks = 0; ks < 4; ks++) {
            uint32_t ah[2][4], al[2][4];
            #pragma unroll
            for (int i = 0; i < 2; i++) {
                uint32_t ao = cur + AH + (uint32_t)((warp_m + 16 * i + arow) * LDA + ks * 16 + acol8) * 2;
                ldsm_x4(ah[i], sb + ao);
                if (PASSES == 3) ldsm_x4(al[i], sb + ao + (AL - AH));
            }
            uint32_t bh[2][4], bl[2][4];
            #pragma unroll
            for (int jp = 0; jp < 2; jp++) {
                uint32_t bo = cur + BH + (uint32_t)((ks * 16 + brow) * LDB + warp_n + 16 * jp + bco) * 2;
                ldsm_x4t(bh[jp], sb + bo);
                if (PASSES == 3) ldsm_x4t(bl[jp], sb + bo + (BL - BH));
            }
            #pragma unroll
            for (int pass = 0; pass < PASSES; pass++) {
                #pragma unroll
                for (int i = 0; i < 2; i++) {
                    const uint32_t* aa = (pass == 2) ? al[i] : ah[i];
                    #pragma unroll
                    for (int jp = 0; jp < 2; jp++) {
                        const uint32_t* bb = (pass == 1) ? bl[jp] : bh[jp];
                        mma_bf(c[i][2*jp],   aa, bb);
                        mma_bf(c[i][2*jp+1], aa, bb + 2);
                    }
                }
            }
        }

        if (kc < 3) {
            storeChunk((kc & 1) ? 0 : GEMM_BUF);
            __syncthreads();
        }
    }
}

// ---------------- epilogues ----------------
__device__ __forceinline__ void epi_f32(
    float c[2][4][4], float* __restrict__ Cout, const float* __restrict__ bias,
    int N, int row0, int col0, bool relu, float sc)
{
    const int wid  = threadIdx.x >> 5;
    const int lane = threadIdx.x & 31;
    const int warp_m = (wid & 3) * 32;
    const int warp_n = (wid >> 2) * 32;
    const int g = lane >> 2, t2 = (lane & 3) * 2;
    #pragma unroll
    for (int j = 0; j < 4; j++) {
        int col = col0 + warp_n + 8 * j + t2;
        if (col >= N) continue;
        float2 b2 = make_float2(0.f, 0.f);
        if (bias) b2 = *(const float2*)(bias + col);
        #pragma unroll
        for (int i = 0; i < 2; i++) {
            int rl = row0 + warp_m + 16 * i + g;
            float2 v0 = make_float2(c[i][j][0] * sc + b2.x, c[i][j][1] * sc + b2.y);
            float2 v1 = make_float2(c[i][j][2] * sc + b2.x, c[i][j][3] * sc + b2.y);
            if (relu) {
                v0.x = fmaxf(v0.x, 0.f); v0.y = fmaxf(v0.y, 0.f);
                v1.x = fmaxf(v1.x, 0.f); v1.y = fmaxf(v1.y, 0.f);
            }
            *(float2*)(Cout + (size_t)rl * N + col)       = v0;
            *(float2*)(Cout + (size_t)(rl + 8) * N + col) = v1;
        }
    }
}

__device__ __forceinline__ void epi_hi(
    float c[2][4][4], u16* __restrict__ Ho, const float* __restrict__ bias,
    float sc, bool relu, int row0, int col0)
{
    const int wid  = threadIdx.x >> 5;
    const int lane = threadIdx.x & 31;
    const int warp_m = (wid & 3) * 32;
    const int warp_n = (wid >> 2) * 32;
    const int g = lane >> 2, t2 = (lane & 3) * 2;
    #pragma unroll
    for (int j = 0; j < 4; j++) {
        int col = col0 + warp_n + 8 * j + t2;
        float2 b2 = make_float2(0.f, 0.f);
        if (bias) b2 = *(const float2*)(bias + col);
        #pragma unroll
        for (int i = 0; i < 2; i++) {
            int rl = row0 + warp_m + 16 * i + g;
            float v0 = (c[i][j][0] + b2.x) * sc, v1 = (c[i][j][1] + b2.y) * sc;
            float v2 = (c[i][j][2] + b2.x) * sc, v3 = (c[i][j][3] + b2.y) * sc;
            if (relu) {
                v0 = fmaxf(v0, 0.f); v1 = fmaxf(v1, 0.f);
                v2 = fmaxf(v2, 0.f); v3 = fmaxf(v3, 0.f);
            }
            *(uint32_t*)(Ho + (size_t)rl * 256 + col)       = pack_bf16x2(v0, v1);
            *(uint32_t*)(Ho + (size_t)(rl + 8) * 256 + col) = pack_bf16x2(v2, v3);
        }
    }
}

__device__ __forceinline__ void epi_pair(
    float c[2][4][4], u16* __restrict__ Ho, u16* __restrict__ Lo,
    const float* __restrict__ bias, int row0, int col0)
{
    const int wid  = threadIdx.x >> 5;
    const int lane = threadIdx.x & 31;
    const int warp_m = (wid & 3) * 32;
    const int warp_n = (wid >> 2) * 32;
    const int g = lane >> 2, t2 = (lane & 3) * 2;
    #pragma unroll
    for (int j = 0; j < 4; j++) {
        int col = col0 + warp_n + 8 * j + t2;
        float2 b2 = make_float2(0.f, 0.f);
        if (bias) b2 = *(const float2*)(bias + col);
        #pragma unroll
        for (int i = 0; i < 2; i++) {
            int rl = row0 + warp_m + 16 * i + g;
            float v0 = c[i][j][0] + b2.x, v1 = c[i][j][1] + b2.y;
            float v2 = c[i][j][2] + b2.x, v3 = c[i][j][3] + b2.y;
            uint32_t h0 = pack_bf16x2(v0, v1);
            uint32_t l0 = pack_bf16x2(v0 - bf_lo_f(h0), v1 - bf_hi_f(h0));
            uint32_t h1 = pack_bf16x2(v2, v3);
            uint32_t l1 = pack_bf16x2(v2 - bf_lo_f(h1), v3 - bf_hi_f(h1));
            *(uint32_t*)(Ho + (size_t)rl * 256 + col)       = h0;
            *(uint32_t*)(Lo + (size_t)rl * 256 + col)       = l0;
            *(uint32_t*)(Ho + (size_t)(rl + 8) * 256 + col) = h1;
            *(uint32_t*)(Lo + (size_t)(rl + 8) * 256 + col) = l1;
        }
    }
}

// ---------------- GEMM kernels ----------------
__global__ __launch_bounds__(512, 1) void gemm13bf(
    const float* __restrict__ query, const float* __restrict__ w1,
    const float* __restrict__ value, const float* __restrict__ w3)
{
    extern __shared__ char smem[];
    const int sel  = blockIdx.x >> 1;
    const int col0 = (blockIdx.x & 1) * 128;
    const int row0 = blockIdx.y * 128;
    if (sel == 0) {
        float c[2][4][4] = {};
        gemm_main<1, 0>(query, nullptr, w1, 256, row0, col0, smem, smem_u32(smem), c);
        epi_hi(c, g_t1h, nullptr, 1.f, true, row0, col0);
    } else {
        float c[2][4][4] = {};
        gemm_main<3, 0>(value, nullptr, w3, 256, row0, col0, smem, smem_u32(smem), c);
        epi_pair(c, g_vwh, g_vwl, nullptr, row0, col0);   // V pair for tensor-core ldsa
    }
}

__global__ __launch_bounds__(512, 1) void gemm_w2k(const float* __restrict__ w2)
{
    extern __shared__ char smem[];
    const int col0 = blockIdx.x * 104;
    const int row0 = blockIdx.y * 128;
    float c[2][4][4] = {};
    gemm_main<1, 1>(g_t1h, nullptr, w2, WN, row0, col0, smem, smem_u32(smem), c);
    epi_f32(c, g_w, nullptr, WN, row0, col0, false, LOG2E);
}

__global__ __launch_bounds__(512, 1) void gemm_wlk(const float* __restrict__ wl)
{
    extern __shared__ char smem[];
    const int col0 = blockIdx.x * 128;
    const int row0 = blockIdx.y * 128;
    float c[2][4][4] = {};
    gemm_main<3, 2>(g_xlh, g_xll, wl, 256, row0, col0, smem, smem_u32(smem), c);
    epi_pair(c, g_xh, g_xl2, nullptr, row0, col0);
}

__global__ __launch_bounds__(512, 1) void qkv_bf(
    const float* __restrict__ wq, const float* __restrict__ bq,
    const float* __restrict__ wk, const float* __restrict__ bk,
    const float* __restrict__ wv, const float* __restrict__ bv)
{
    extern __shared__ char smem[];
    const int wsel = blockIdx.x >> 1;
    const int col0 = (blockIdx.x & 1) * 128;
    const int row0 = blockIdx.y * 128;
    if (wsel == 0) {
        float c[2][4][4] = {};
        gemm_main<1, 1>(g_xh, nullptr, wq, 256, row0, col0, smem, smem_u32(smem), c);
        epi_hi(c, g_qh, bq, SCALE_Q, false, row0, col0);
    } else if (wsel == 1) {
        float c[2][4][4] = {};
        gemm_main<1, 1>(g_xh, nullptr, wk, 256, row0, col0, smem, smem_u32(smem), c);
        epi_hi(c, g_kh, bk, 1.f, false, row0, col0);
    } else {
        float c[2][4][4] = {};
        gemm_main<3, 2>(g_xh, g_xl2, wv, 256, row0, col0, smem, smem_u32(smem), c);
        epi_pair(c, g_vh, g_vlo, bv, row0, col0);
    }
}

__global__ __launch_bounds__(512, 1) void gemm_wok(
    const float* __restrict__ wo, const float* __restrict__ bo, float* __restrict__ out)
{
    extern __shared__ char smem[];
    const int col0 = blockIdx.x * 128;
    const int row0 = blockIdx.y * 128;
    float c[2][4][4] = {};
    gemm_main<3, 2>(g_oh, g_ol, wo, 256, row0, col0, smem, smem_u32(smem), c);
    epi_f32(c, out, bo, 256, row0, col0, false, 1.f);
}

// ---------------------------------------------------------------------------
// LDSA on tensor cores: banded softmax P (64 x 144 window, dense hi/lo bf16)
// then O = P @ Vwin via bf16x3 mma. 256 threads, 2 CTAs/SM.
// Band: row r covers window cols jj = r .. r+77 (jj = (t - (t0-38)) for c).
// ---------------------------------------------------------------------------
constexpr int LDP = 152;                                // P row stride (u16)
constexpr uint32_t PH_O = 0, PL_O = 19456;              // 64*152*2 each
constexpr uint32_t VWH_O = 38912, VWL_O = 59648;        // 144*72*2 each
constexpr int LDSA_SMEM = 80384;

__global__ __launch_bounds__(256, 2) void ldsa_mma()
{
    extern __shared__ char smem[];
    const uint32_t sb = smem_u32(smem);
    const int bh = blockIdx.y;
    const int b = bh >> 2, h = bh & 3;
    const int t0 = blockIdx.x * 64;
    const int tid = threadIdx.x, wid = tid >> 5, lane = tid & 31;

    // zero P (PH+PL contiguous = 38912 B = 2432 uint4)
    for (int i = tid; i < 2432; i += 256)
        ((uint4*)smem)[i] = make_uint4(0, 0, 0, 0);

    // stage V window rows jj = 0..143 (global j = t0 - 38 + jj)
    for (int i = tid; i < 144 * 8; i += 256) {
        int r = i >> 3, d8 = (i & 7) * 8;
        int j = t0 - HALF + r;
        uint32_t so = (uint32_t)(r * 72 + d8) * 2;
        if (j >= 0 && j < T && r < 141) {
            size_t go = (size_t)(b * T + j) * 256 + h * 64 + d8;
            cp16(sb + VWH_O + so, g_vwh + go);
            cp16(sb + VWL_O + so, g_vwl + go);
        } else {
            *(uint4*)(smem + VWH_O + so) = make_uint4(0, 0, 0, 0);
            *(uint4*)(smem + VWL_O + so) = make_uint4(0, 0, 0, 0);
        }
    }
    cp_commit();
    __syncthreads();   // P zeros visible before scatter

    // softmax -> dense banded P (hi/lo). warp per row, 8 iterations.
    for (int it = 0; it < 8; it++) {
        const int r = it * 8 + wid;
        const int t = t0 + r;
        float e[3];
        float s = 0.f;
        #pragma unroll
        for (int u = 0; u < 3; u++) {
            int c = lane + u * 32;
            float val = -3.0e38f;
            if (c < C) {
                int j = t - HALF + c;
                if (j >= 0 && j < T)
                    val = g_w[(size_t)(b * T + t) * WN + h * C + c];
            }
            e[u] = exp2f(val);   // invalid -> 0
            s += e[u];
        }
        #pragma unroll
        for (int off = 16; off > 0; off >>= 1)
            s += __shfl_xor_sync(0xffffffffu, s, off);
        const float inv = 1.f / s;
        #pragma unroll
        for (int u = 0; u < 3; u++) {
            int c = lane + u * 32;
            if (c < C) {
                float p = e[u] * inv;
                __nv_bfloat16 hb = __float2bfloat16(p);
                __nv_bfloat16 lb = __float2bfloat16(p - __bfloat162float(hb));
                uint32_t off2 = (uint32_t)(r * LDP + r + c) * 2;   // jj = r + c
                *(u16*)(smem + PH_O + off2) = __bfloat16_as_ushort(hb);
                *(u16*)(smem + PL_O + off2) = __bfloat16_as_ushort(lb);
            }
        }
    }
    cp_wait<0>();
    __syncthreads();

    // O = P @ Vwin, K = 144 (9 x k16), warp tile 16 rows x 32 cols (4m x 2n)
    const int wm = wid & 3;
    const int wn = (wid >> 2) * 32;
    const int arow = lane & 15, acol8 = (lane >> 4) * 8;
    const int vco = (lane & 16) >> 1;
    float cacc[4][4] = {};
    #pragma unroll
    for (int ks = 0; ks < 9; ks++) {
        uint32_t ap[4], al[4];
        uint32_t ao = (uint32_t)((16 * wm + arow) * LDP + ks * 16 + acol8) * 2;
        ldsm_x4(ap, sb + PH_O + ao);
        ldsm_x4(al, sb + PL_O + ao);
        uint32_t vh[2][4], vl[2][4];
        #pragma unroll
        for (int jp = 0; jp < 2; jp++) {
            uint32_t vo = (uint32_t)((ks * 16 + (lane & 15)) * 72 + wn + 16 * jp + vco) * 2;
            ldsm_x4t(vh[jp], sb + VWH_O + vo);
            ldsm_x4t(vl[jp], sb + VWL_O + vo);
        }
        #pragma unroll
        for (int pass = 0; pass < 3; pass++) {
            const uint32_t* aa = (pass == 2) ? al : ap;
            #pragma unroll
            for (int jp = 0; jp < 2; jp++) {
                const uint32_t* bb = (pass == 1) ? vl[jp] : vh[jp];
                mma_bf(cacc[2*jp],   aa, bb);
                mma_bf(cacc[2*jp+1], aa, bb + 2);
            }
        }
    }

    // epilogue: write xl pair
    const int g = lane >> 2, t2 = (lane & 3) * 2;
    const int r0 = t0 + 16 * wm + g;
    #pragma unroll
    for (int j = 0; j < 4; j++) {
        int col = h * DK + wn + 8 * j + t2;
        float v0 = cacc[j][0], v1 = cacc[j][1];
        float v2 = cacc[j][2], v3 = cacc[j][3];
        uint32_t h0 = pack_bf16x2(v0, v1);
        uint32_t l0 = pack_bf16x2(v0 - bf_lo_f(h0), v1 - bf_hi_f(h0));
        uint32_t h1 = pack_bf16x2(v2, v3);
        uint32_t l1 = pack_bf16x2(v2 - bf_lo_f(h1), v3 - bf_hi_f(h1));
        size_t i0 = (size_t)(b * T + r0) * 256 + col;
        size_t i1 = (size_t)(b * T + r0 + 8) * 256 + col;
        *(uint32_t*)(g_xlh + i0) = h0;
        *(uint32_t*)(g_xll + i0) = l0;
        *(uint32_t*)(g_xlh + i1) = h1;
        *(uint32_t*)(g_xll + i1) = l1;
    }
}

// ---------------------------------------------------------------------------
// Flash-attention MHA (R15 best: 256 threads, triple-buffered K/V, one
// barrier per tile, no-max softmax, Q-hoist, 1-pass S / 3-pass PV).
// ---------------------------------------------------------------------------
constexpr int KV_BUF     = 55296;                 // KH | VH | VL, 18432 each
constexpr int FLASH_SMEM = 18432 + 3 * KV_BUF;    // 184320

__global__ __launch_bounds__(256, 1) void flash_mma()
{
    extern __shared__ char smem[];
    const uint32_t sb = smem_u32(smem);
    constexpr uint32_t QH = 0, KV0 = 18432;
    constexpr int LDS = 72;

    const int bh = blockIdx.y;
    const int b = bh >> 2;
    const int h = bh & 3;
    const int t0 = blockIdx.x * 128;
    const int tid  = threadIdx.x;
    const int wid  = tid >> 5;
    const int lane = tid & 31;
    const int g  = lane >> 2;
    const int t2 = (lane & 3) * 2;

    for (int i = tid; i < 1024; i += 256) {
        int r = i >> 3, d8 = (i & 7) * 8;
        size_t go = (size_t)(b * T + t0 + r) * 256 + h * 64 + d8;
        *(uint4*)(smem + QH + (uint32_t)(r * LDS + d8) * 2) = *(const uint4*)(g_qh + go);
    }

    auto prefetchKV = [&](int st) {
        const uint32_t base = KV0 + (uint32_t)(st % 3) * KV_BUF;
        const int s0 = st * 128;
        #pragma unroll
        for (int p = 0; p < 4; p++) {
            int i = tid + p * 256;
            int r = i >> 3, d8 = (i & 7) * 8;
            size_t go = (size_t)(b * T + s0 + r) * 256 + h * 64 + d8;
            uint32_t so = base + (uint32_t)(r * LDS + d8) * 2;
            cp16(sb + so,         g_kh  + go);
            cp16(sb + so + 18432, g_vh  + go);
            cp16(sb + so + 36864, g_vlo + go);
        }
        cp_commit();
    };

    prefetchKV(0);
    prefetchKV(1);
    __syncthreads();

    const int arow = lane & 15, acol8 = (lane >> 4) * 8;
    const int brow2 = (lane & 7) | ((lane & 16) >> 1);
    const int bco = lane & 8;
    const int vco = (lane & 16) >> 1;

    uint32_t qf[4][4];
    #pragma unroll
    for (int ks = 0; ks < 4; ks++)
        ldsm_x4(qf[ks], sb + QH + (uint32_t)((16 * wid + arow) * LDS + ks * 16 + acol8) * 2);

    float o[8][4] = {};
    float l0 = 0.f, l1 = 0.f;

    for (int st = 0; st < 16; st++) {
        if (st < 15) cp_wait<1>();
        else         cp_wait<0>();
        __syncthreads();
        if (st + 2 < 16) prefetchKV(st + 2);

        const uint32_t KHb = sb + KV0 + (uint32_t)(st % 3) * KV_BUF;
        const uint32_t VHb = KHb + 18432, VLb = KHb + 36864;

        float s[16][4] = {};
        #pragma unroll
        for (int ks = 0; ks < 4; ks++) {
            #pragma unroll
            for (int jp = 0; jp < 8; jp++) {
                uint32_t kh[4];
                ldsm_x4(kh, KHb + (uint32_t)((16 * jp + brow2) * LDS + ks * 16 + bco) * 2);
                mma_bf(s[2*jp],   qf[ks], kh);
                mma_bf(s[2*jp+1], qf[ks], kh + 2);
            }
        }

        float rs0 = 0.f, rs1 = 0.f;
        uint32_t ph[8][4], pl[8][4];
        #pragma unroll
        for (int kb = 0; kb < 8; kb++) {
            float e00 = exp2f(s[2*kb][0]),   e01 = exp2f(s[2*kb][1]);
            float e02 = exp2f(s[2*kb][2]),   e03 = exp2f(s[2*kb][3]);
            float e10 = exp2f(s[2*kb+1][0]), e11 = exp2f(s[2*kb+1][1]);
            float e12 = exp2f(s[2*kb+1][2]), e13 = exp2f(s[2*kb+1][3]);
            rs0 += e00 + e01 + e10 + e11;
            rs1 += e02 + e03 + e12 + e13;
            ph[kb][0] = pack_bf16x2(e00, e01);
            ph[kb][1] = pack_bf16x2(e02, e03);
            ph[kb][2] = pack_bf16x2(e10, e11);
            ph[kb][3] = pack_bf16x2(e12, e13);
            pl[kb][0] = pack_bf16x2(e00 - bf_lo_f(ph[kb][0]), e01 - bf_hi_f(ph[kb][0]));
            pl[kb][1] = pack_bf16x2(e02 - bf_lo_f(ph[kb][1]), e03 - bf_hi_f(ph[kb][1]));
            pl[kb][2] = pack_bf16x2(e10 - bf_lo_f(ph[kb][2]), e11 - bf_hi_f(ph[kb][2]));
            pl[kb][3] = pack_bf16x2(e12 - bf_lo_f(ph[kb][3]), e13 - bf_hi_f(ph[kb][3]));
        }
        rs0 += __shfl_xor_sync(0xffffffffu, rs0, 1);
        rs0 += __shfl_xor_sync(0xffffffffu, rs0, 2);
        rs1 += __shfl_xor_sync(0xffffffffu, rs1, 1);
        rs1 += __shfl_xor_sync(0xffffffffu, rs1, 2);
        l0 += rs0;
        l1 += rs1;

        #pragma unroll
        for (int ks = 0; ks < 8; ks++) {
            uint32_t vh[4][4], vl[4][4];
            #pragma unroll
            for (int jp = 0; jp < 4; jp++) {
                uint32_t vo = (uint32_t)((ks * 16 + (lane & 15)) * LDS + 16 * jp + vco) * 2;
                ldsm_x4t(vh[jp], VHb + vo);
                ldsm_x4t(vl[jp], VLb + vo);
            }
            #pragma unroll
            for (int pass = 0; pass < 3; pass++) {
                const uint32_t* pa = (pass == 2) ? pl[ks] : ph[ks];
                #pragma unroll
                for (int jp = 0; jp < 4; jp++) {
                    const uint32_t* vb = (pass == 1) ? vl[jp] : vh[jp];
                    mma_bf(o[2*jp],   pa, vb);
                    mma_bf(o[2*jp+1], pa, vb + 2);
                }
            }
        }
    }

    const float inv0 = 1.f / l0, inv1 = 1.f / l1;
    const int r0 = t0 + 16 * wid + g;
    #pragma unroll
    for (int j = 0; j < 8; j++) {
        int col = h * DK + 8 * j + t2;
        float v0 = o[j][0] * inv0, v1 = o[j][1] * inv0;
        float v2 = o[j][2] * inv1, v3 = o[j][3] * inv1;
        uint32_t h0  = pack_bf16x2(v0, v1);
        uint32_t l0p = pack_bf16x2(v0 - bf_lo_f(h0), v1 - bf_hi_f(h0));
        uint32_t h1  = pack_bf16x2(v2, v3);
        uint32_t l1p = pack_bf16x2(v2 - bf_lo_f(h1), v3 - bf_hi_f(h1));
        size_t i0 = (size_t)(b * T + r0) * F + col;
        size_t i1 = (size_t)(b * T + r0 + 8) * F + col;
        *(uint32_t*)(g_oh + i0) = h0;
        *(uint32_t*)(g_ol + i0) = l0p;
        *(uint32_t*)(g_oh + i1) = h1;
        *(uint32_t*)(g_ol + i1) = l1p;
    }
}

// ---------------------------------------------------------------------------
extern "C" void kernel_launch(void* const* d_in, const int* in_sizes, int n_in,
                              void* d_out, int out_size)
{
    const float* query  = (const float*)d_in[0];
    const float* value  = (const float*)d_in[2];
    const float* w1     = (const float*)d_in[4];
    const float* w2     = (const float*)d_in[5];
    const float* w3     = (const float*)d_in[6];
    const float* w_ldsa = (const float*)d_in[7];
    const float* wq     = (const float*)d_in[8];
    const float* bq     = (const float*)d_in[9];
    const float* wk     = (const float*)d_in[10];
    const float* bk     = (const float*)d_in[11];
    const float* wv     = (const float*)d_in[12];
    const float* bv     = (const float*)d_in[13];
    const float* wo     = (const float*)d_in[14];
    const float* bo     = (const float*)d_in[15];
    float* out = (float*)d_out;

    cudaFuncSetAttribute(gemm13bf,  cudaFuncAttributeMaxDynamicSharedMemorySize, GEMM_SMEM);
    cudaFuncSetAttribute(gemm_w2k,  cudaFuncAttributeMaxDynamicSharedMemorySize, GEMM_SMEM);
    cudaFuncSetAttribute(gemm_wlk,  cudaFuncAttributeMaxDynamicSharedMemorySize, GEMM_SMEM);
    cudaFuncSetAttribute(qkv_bf,    cudaFuncAttributeMaxDynamicSharedMemorySize, GEMM_SMEM);
    cudaFuncSetAttribute(gemm_wok,  cudaFuncAttributeMaxDynamicSharedMemorySize, GEMM_SMEM);
    cudaFuncSetAttribute(ldsa_mma,  cudaFuncAttributeMaxDynamicSharedMemorySize, LDSA_SMEM);
    cudaFuncSetAttribute(flash_mma, cudaFuncAttributeMaxDynamicSharedMemorySize, FLASH_SMEM);

    // LDSA stage
    gemm13bf<<<dim3(4, M / 128), 512, GEMM_SMEM>>>(query, w1, value, w3);
    gemm_w2k<<<dim3(3, M / 128), 512, GEMM_SMEM>>>(w2);
    ldsa_mma<<<dim3(T / 64, Bb * H), 256, LDSA_SMEM>>>();
    gemm_wlk<<<dim3(2, M / 128), 512, GEMM_SMEM>>>(w_ldsa);

    // MHA stage
    qkv_bf<<<dim3(6, M / 128), 512, GEMM_SMEM>>>(wq, bq, wk, bk, wv, bv);
    flash_mma<<<dim3(T / 128, Bb * H), 256, FLASH_SMEM>>>();
    gemm_wok<<<dim3(2, M / 128), 512, GEMM_SMEM>>>(wo, bo, out);
}